// round 11
// baseline (speedup 1.0000x reference)
#include <cuda_runtime.h>
#include <cstdint>

#define SEQ 256
#define VOC 96
#define DD  (SEQ * VOC)     // 24576 dendrites
#define TPITCH 128          // padded row bytes (96 payload)

// int8 quantized log-weight table + one zero row (3.1 MB, L2-resident).
__device__ __align__(16) signed char g_tab[(DD + 1) * TPITCH];

#define QSCALE   (0.625f / 127.0f)
#define QINV     (127.0f / 0.625f)

// PRMT with sign-replicate mode (bit 3 of nibble) — must be inline asm,
// __byte_perm masks selector nibbles to 3 bits.
template <unsigned SEL>
__device__ __forceinline__ unsigned prmt_sx(unsigned a) {
    unsigned r;
    asm("prmt.b32 %0, %1, 0, %2;" : "=r"(r) : "r"(a), "n"(SEL));
    return r;
}

// log(2*sigmoid(x)) = u - logcosh(u), u = x/2;
// logcosh(u) ~= u^2/2 - u^4/12 + u^6/45  (|err| <= 2.6e-5 for |u| <= 0.5).
__device__ __forceinline__ signed char quant_logw(float x) {
    float u = 0.5f * x;
    float w = u * u;
    float lch = w * (0.5f + w * (-0.0833333333f + w * 0.0222222222f));
    int q = __float2int_rn((u - lch) * QINV);
    return (signed char)max(-127, min(127, q));
}

// ---------------------------------------------------------------------------
// Kernel 1: build int8 table, transposed (V,D)->(D,V). Triggers the dependent
// gather launch immediately at entry (PDL): gather blocks start staging while
// this kernel is still transforming.
// ---------------------------------------------------------------------------
__global__ __launch_bounds__(256) void transform_kernel(const float* __restrict__ raw) {
    cudaTriggerProgrammaticLaunchCompletion();

    __shared__ __align__(16) signed char tile[32][112];  // pitch 112 = 7*16
    const int d0 = blockIdx.x * 32;
    const int t  = threadIdx.x;

    #pragma unroll
    for (int i = t; i < 32 * VOC; i += 256) {
        int v  = i >> 5;
        int dc = i & 31;
        tile[dc][v] = quant_logw(raw[v * DD + d0 + dc]);
    }
    __syncthreads();

    if (t < 32 * 6) {
        int dr = t / 6;
        int j  = t % 6;
        uint4 v = *reinterpret_cast<const uint4*>(&tile[dr][j * 16]);
        *reinterpret_cast<uint4*>(&g_tab[(size_t)(d0 + dr) * TPITCH + j * 16]) = v;
    }
    if (blockIdx.x == 0 && t >= 224 && t < 230) {
        *reinterpret_cast<uint4*>(&g_tab[(size_t)DD * TPITCH + (t - 224) * 16]) =
            make_uint4(0, 0, 0, 0);
    }
}

// ---------------------------------------------------------------------------
// Kernel 2: gather-sum. 384 threads = 4 samples x 16 sixteenths x 6 uint4-
// lanes. Stages chars/offsets BEFORE cudaGridDependencySynchronize() so that
// work overlaps the transform kernel; table reads only after the sync.
// Exact s16x2 accumulation (PRMT sign-extend + VADD2), MLP-4, 4 blocks/SM.
// ---------------------------------------------------------------------------
__global__ __launch_bounds__(384, 4) void gather_kernel(const int* __restrict__ chars,
                                                        float* __restrict__ out, int B) {
    __shared__ int      soff[4 * SEQ];       // [slot][k(16)][sixteenth(16)]
    __shared__ unsigned sfired[4 * 8];
    __shared__ uint4    sredA[384];
    __shared__ uint4    sredB[384];

    const int t     = threadIdx.x;
    const int bbase = blockIdx.x * 4;

    // ---- staging: independent of the table -> overlaps transform ----
    #pragma unroll
    for (int kk = 0; kk < 3; kk++) {
        int i = kk * 384 + t;
        int c = 0;
        if (i < 4 * SEQ) {
            int b = bbase + (i >> 8);
            int s = i & (SEQ - 1);
            if (b < B) c = chars[b * SEQ + s];
            int dend = (c > 0) ? (s * VOC + c - 1) : DD;
            // interleaved: [slot][s&15][s>>4] -> conflict-free inner-loop LDS
            soff[(i & ~255) + (s & 15) * 16 + (s >> 4)] = dend * TPITCH;
        }
        unsigned ball = __ballot_sync(0xffffffffu, c > 0);
        if ((t & 31) == 0 && i < 4 * SEQ) sfired[i >> 5] = ball;
    }
    __syncthreads();

    // Wait for the transform kernel's writes to be visible (no-op if this
    // kernel was not launched as a programmatic dependent).
    cudaGridDependencySynchronize();

    const int slot      = t / 96;
    const int sub       = t % 96;
    const int sixteenth = sub / 6;
    const int lane      = sub % 6;

    const char* tb = reinterpret_cast<const char*>(g_tab) + lane * 16;
    const int*  so = &soff[slot * SEQ + sixteenth];

    unsigned acc[8];
    #pragma unroll
    for (int r = 0; r < 8; r++) acc[r] = 0;

    int off[4];
    #pragma unroll
    for (int u = 0; u < 4; u++) off[u] = so[u * 16];

    #pragma unroll
    for (int kb = 0; kb < 16; kb += 4) {
        uint4 v[4];
        #pragma unroll
        for (int u = 0; u < 4; u++)
            v[u] = *reinterpret_cast<const uint4*>(tb + off[u]);
        if (kb + 4 < 16) {
            #pragma unroll
            for (int u = 0; u < 4; u++) off[u] = so[(kb + 4 + u) * 16];
        }
        #pragma unroll
        for (int u = 0; u < 4; u++) {
            acc[0] = __vadd2(acc[0], prmt_sx<0x9180>(v[u].x));
            acc[1] = __vadd2(acc[1], prmt_sx<0xB3A2>(v[u].x));
            acc[2] = __vadd2(acc[2], prmt_sx<0x9180>(v[u].y));
            acc[3] = __vadd2(acc[3], prmt_sx<0xB3A2>(v[u].y));
            acc[4] = __vadd2(acc[4], prmt_sx<0x9180>(v[u].z));
            acc[5] = __vadd2(acc[5], prmt_sx<0xB3A2>(v[u].z));
            acc[6] = __vadd2(acc[6], prmt_sx<0x9180>(v[u].w));
            acc[7] = __vadd2(acc[7], prmt_sx<0xB3A2>(v[u].w));
        }
    }

    sredA[t] = make_uint4(acc[0], acc[1], acc[2], acc[3]);
    sredB[t] = make_uint4(acc[4], acc[5], acc[6], acc[7]);
    __syncthreads();

    int b = bbase + slot;
    if (sixteenth == 0 && b < B) {
        #pragma unroll
        for (int e = 1; e < 16; e++) {
            uint4 a = sredA[t + e * 6];
            uint4 c = sredB[t + e * 6];
            acc[0] = __vadd2(acc[0], a.x); acc[1] = __vadd2(acc[1], a.y);
            acc[2] = __vadd2(acc[2], a.z); acc[3] = __vadd2(acc[3], a.w);
            acc[4] = __vadd2(acc[4], c.x); acc[5] = __vadd2(acc[5], c.y);
            acc[6] = __vadd2(acc[6], c.z); acc[7] = __vadd2(acc[7], c.w);
        }

        int n = 0;
        #pragma unroll
        for (int w = 0; w < 8; w++) n += __popc(sfired[slot * 8 + w]);
        float zm = QSCALE / fmaxf((float)n, 1.0f);

        float o[16];
        #pragma unroll
        for (int r = 0; r < 8; r++) {
            int lo = (int)(short)(acc[r] & 0xFFFF);
            int hi = ((int)acc[r]) >> 16;
            int j = r >> 1, p = (r & 1) * 2;
            o[j * 4 + p]     = __expf((float)lo * zm);
            o[j * 4 + p + 1] = __expf((float)hi * zm);
        }
        float4* po = reinterpret_cast<float4*>(out + b * VOC + lane * 16);
        po[0] = make_float4(o[0],  o[1],  o[2],  o[3]);
        po[1] = make_float4(o[4],  o[5],  o[6],  o[7]);
        po[2] = make_float4(o[8],  o[9],  o[10], o[11]);
        po[3] = make_float4(o[12], o[13], o[14], o[15]);
    }
}

// ---------------------------------------------------------------------------
extern "C" void kernel_launch(void* const* d_in, const int* in_sizes, int n_in,
                              void* d_out, int out_size) {
    const int*   chars;
    const float* raw;
    int csz;
    if (in_sizes[0] == VOC * DD) {
        raw   = (const float*)d_in[0];
        chars = (const int*)d_in[1];
        csz   = in_sizes[1];
    } else {
        chars = (const int*)d_in[0];
        raw   = (const float*)d_in[1];
        csz   = in_sizes[0];
    }
    const int B = csz / SEQ;
    const int G = (B + 3) / 4;

    transform_kernel<<<DD / 32, 256>>>(raw);

    // PDL launch: gather begins (and stages its offsets) while transform runs;
    // cudaGridDependencySynchronize() inside orders the table reads.
    cudaLaunchConfig_t cfg = {};
    cfg.gridDim  = dim3((unsigned)G);
    cfg.blockDim = dim3(384);
    cfg.dynamicSmemBytes = 0;
    cfg.stream = 0;
    cudaLaunchAttribute attr[1];
    attr[0].id = cudaLaunchAttributeProgrammaticStreamSerialization;
    attr[0].val.programmaticStreamSerializationAllowed = 1;
    cfg.attrs = attr;
    cfg.numAttrs = 1;

    cudaError_t e = cudaLaunchKernelEx(&cfg, gather_kernel,
                                       chars, (float*)d_out, B);
    if (e != cudaSuccess) {
        // Fallback: plain dependent launch (sync inside is then a no-op).
        gather_kernel<<<G, 384>>>(chars, (float*)d_out, B);
    }
}

// round 12
// speedup vs baseline: 1.2931x; 1.2931x over previous
#include <cuda_runtime.h>
#include <cstdint>

#define SEQ 256
#define VOC 96
#define DD  (SEQ * VOC)     // 24576 dendrites
#define TPITCH 128          // padded row bytes (96 payload)

// int8 quantized log-weight table + one zero row (3.1 MB, L2-resident).
__device__ __align__(16) signed char g_tab[(DD + 1) * TPITCH];

#define QSCALE   (0.625f / 127.0f)
#define QINV     (127.0f / 0.625f)

// PRMT with sign-replicate mode (bit 3 of nibble) — must be inline asm,
// __byte_perm masks selector nibbles to 3 bits.
template <unsigned SEL>
__device__ __forceinline__ unsigned prmt_sx(unsigned a) {
    unsigned r;
    asm("prmt.b32 %0, %1, 0, %2;" : "=r"(r) : "r"(a), "n"(SEL));
    return r;
}

// log(2*sigmoid(x)) = u - logcosh(u), u = x/2;
// logcosh(u) ~= u^2/2 - u^4/12 + u^6/45  (|err| <= 2.6e-5 for |u| <= 0.5).
__device__ __forceinline__ signed char quant_logw(float x) {
    float u = 0.5f * x;
    float w = u * u;
    float lch = w * (0.5f + w * (-0.0833333333f + w * 0.0222222222f));
    int q = __float2int_rn((u - lch) * QINV);
    return (signed char)max(-127, min(127, q));
}

// ---------------------------------------------------------------------------
// Kernel 1: build int8 table, transposed (V,D)->(D,V). Pure-FMA math,
// DRAM-bound (~12.5 MB). 768 blocks x 256 threads.
// ---------------------------------------------------------------------------
__global__ __launch_bounds__(256) void transform_kernel(const float* __restrict__ raw) {
    __shared__ __align__(16) signed char tile[32][112];  // pitch 112 = 7*16
    const int d0 = blockIdx.x * 32;
    const int t  = threadIdx.x;

    #pragma unroll
    for (int i = t; i < 32 * VOC; i += 256) {
        int v  = i >> 5;
        int dc = i & 31;
        tile[dc][v] = quant_logw(raw[v * DD + d0 + dc]);
    }
    __syncthreads();

    if (t < 32 * 6) {
        int dr = t / 6;
        int j  = t % 6;
        uint4 v = *reinterpret_cast<const uint4*>(&tile[dr][j * 16]);
        *reinterpret_cast<uint4*>(&g_tab[(size_t)(d0 + dr) * TPITCH + j * 16]) = v;
    }
    if (blockIdx.x == 0 && t >= 224 && t < 230) {
        *reinterpret_cast<uint4*>(&g_tab[(size_t)DD * TPITCH + (t - 224) * 16]) =
            make_uint4(0, 0, 0, 0);
    }
}

// ---------------------------------------------------------------------------
// Kernel 2: gather-sum. 384 threads = 4 samples x 16 sixteenths x 6 uint4-
// lanes (16 classes each). Branchless (zero row), exact s16x2 accumulation
// (PRMT sign-extend + VADD2). __launch_bounds__(384,5): 5 blocks/SM = 60
// warps/SM (regs capped at 34) for deeper latency hiding of L2-resident
// gathers. Grid 512 -> single wave at 740-block capacity.
// ---------------------------------------------------------------------------
__global__ __launch_bounds__(384, 5) void gather_kernel(const int* __restrict__ chars,
                                                        float* __restrict__ out, int B) {
    __shared__ int      soff[4 * SEQ];       // [slot][k(16)][sixteenth(16)]
    __shared__ unsigned sfired[4 * 8];
    __shared__ uint4    sredA[384];
    __shared__ uint4    sredB[384];

    const int t     = threadIdx.x;
    const int bbase = blockIdx.x * 4;

    // ---- staging: offsets + fired ballots ----
    #pragma unroll
    for (int kk = 0; kk < 3; kk++) {
        int i = kk * 384 + t;
        int c = 0;
        if (i < 4 * SEQ) {
            int b = bbase + (i >> 8);
            int s = i & (SEQ - 1);
            if (b < B) c = chars[b * SEQ + s];
            int dend = (c > 0) ? (s * VOC + c - 1) : DD;
            // interleaved: [slot][s&15][s>>4] -> conflict-free inner-loop LDS
            soff[(i & ~255) + (s & 15) * 16 + (s >> 4)] = dend * TPITCH;
        }
        unsigned ball = __ballot_sync(0xffffffffu, c > 0);
        if ((t & 31) == 0 && i < 4 * SEQ) sfired[i >> 5] = ball;
    }
    __syncthreads();

    const int slot      = t / 96;
    const int sub       = t % 96;
    const int sixteenth = sub / 6;
    const int lane      = sub % 6;

    const char* tb = reinterpret_cast<const char*>(g_tab) + lane * 16;
    const int*  so = &soff[slot * SEQ + sixteenth];

    unsigned acc[8];
    #pragma unroll
    for (int r = 0; r < 8; r++) acc[r] = 0;

    #pragma unroll
    for (int kb = 0; kb < 16; kb += 4) {
        uint4 v[4];
        #pragma unroll
        for (int u = 0; u < 4; u++)
            v[u] = *reinterpret_cast<const uint4*>(tb + so[(kb + u) * 16]);
        #pragma unroll
        for (int u = 0; u < 4; u++) {
            acc[0] = __vadd2(acc[0], prmt_sx<0x9180>(v[u].x));
            acc[1] = __vadd2(acc[1], prmt_sx<0xB3A2>(v[u].x));
            acc[2] = __vadd2(acc[2], prmt_sx<0x9180>(v[u].y));
            acc[3] = __vadd2(acc[3], prmt_sx<0xB3A2>(v[u].y));
            acc[4] = __vadd2(acc[4], prmt_sx<0x9180>(v[u].z));
            acc[5] = __vadd2(acc[5], prmt_sx<0xB3A2>(v[u].z));
            acc[6] = __vadd2(acc[6], prmt_sx<0x9180>(v[u].w));
            acc[7] = __vadd2(acc[7], prmt_sx<0xB3A2>(v[u].w));
        }
    }

    sredA[t] = make_uint4(acc[0], acc[1], acc[2], acc[3]);
    sredB[t] = make_uint4(acc[4], acc[5], acc[6], acc[7]);
    __syncthreads();

    int b = bbase + slot;
    if (sixteenth == 0 && b < B) {
        #pragma unroll
        for (int e = 1; e < 16; e++) {
            uint4 a = sredA[t + e * 6];
            uint4 c = sredB[t + e * 6];
            acc[0] = __vadd2(acc[0], a.x); acc[1] = __vadd2(acc[1], a.y);
            acc[2] = __vadd2(acc[2], a.z); acc[3] = __vadd2(acc[3], a.w);
            acc[4] = __vadd2(acc[4], c.x); acc[5] = __vadd2(acc[5], c.y);
            acc[6] = __vadd2(acc[6], c.z); acc[7] = __vadd2(acc[7], c.w);
        }

        int n = 0;
        #pragma unroll
        for (int w = 0; w < 8; w++) n += __popc(sfired[slot * 8 + w]);
        float zm = QSCALE / fmaxf((float)n, 1.0f);

        float o[16];
        #pragma unroll
        for (int r = 0; r < 8; r++) {
            int lo = (int)(short)(acc[r] & 0xFFFF);
            int hi = ((int)acc[r]) >> 16;
            int j = r >> 1, p = (r & 1) * 2;
            o[j * 4 + p]     = __expf((float)lo * zm);
            o[j * 4 + p + 1] = __expf((float)hi * zm);
        }
        float4* po = reinterpret_cast<float4*>(out + b * VOC + lane * 16);
        po[0] = make_float4(o[0],  o[1],  o[2],  o[3]);
        po[1] = make_float4(o[4],  o[5],  o[6],  o[7]);
        po[2] = make_float4(o[8],  o[9],  o[10], o[11]);
        po[3] = make_float4(o[12], o[13], o[14], o[15]);
    }
}

// ---------------------------------------------------------------------------
extern "C" void kernel_launch(void* const* d_in, const int* in_sizes, int n_in,
                              void* d_out, int out_size) {
    const int*   chars;
    const float* raw;
    int csz;
    if (in_sizes[0] == VOC * DD) {
        raw   = (const float*)d_in[0];
        chars = (const int*)d_in[1];
        csz   = in_sizes[1];
    } else {
        chars = (const int*)d_in[0];
        raw   = (const float*)d_in[1];
        csz   = in_sizes[0];
    }
    const int B = csz / SEQ;
    const int G = (B + 3) / 4;

    transform_kernel<<<DD / 32, 256>>>(raw);
    gather_kernel<<<G, 384>>>(chars, (float*)d_out, B);
}